// round 1
// baseline (speedup 1.0000x reference)
#include <cuda_runtime.h>
#include <math.h>

#define N_TOK 4096
#define C 256
#define H 1024
#define E 32
#define ROUTED 31
#define TT 32
#define MAXT 4096
#define PAD (TT + 4)   // 36 floats/row -> 144B stride, 16B aligned, low bank conflict

// ---- device scratch (no allocation allowed) ----
__device__ int   g_counts[E];
__device__ int   g_tok[E * MAXT];     // token index | (slot << 16)
__device__ float g_gw [E * MAXT];     // gate weight
__device__ float g_scratch[4 * N_TOK * C];   // [slot][n][c], 16MB

__global__ void zero_counts_kernel() {
    if (threadIdx.x < E) g_counts[threadIdx.x] = 0;
}

// ---------------- Router: 1 warp per token ----------------
__global__ void router_kernel(const float* __restrict__ x,
                              const float* __restrict__ gW,
                              const float* __restrict__ gb,
                              const float* __restrict__ ebias,
                              float* __restrict__ rw, int write_rw)
{
    const unsigned FULL = 0xffffffffu;
    int n    = blockIdx.x;
    int lane = threadIdx.x;

    __shared__ float xrow[C];
    for (int i = lane; i < C; i += 32) xrow[i] = x[n * C + i];
    __syncwarp();

    float logit = -1e30f;
    if (lane < ROUTED) {
        float acc = gb[lane];
        #pragma unroll 8
        for (int k = 0; k < C; k++) acc = fmaf(xrow[k], gW[k * ROUTED + lane], acc);
        logit = acc;
    }

    // softmax over 31 routed logits
    float m = logit;
    #pragma unroll
    for (int off = 16; off; off >>= 1) m = fmaxf(m, __shfl_xor_sync(FULL, m, off));
    float ev = (lane < ROUTED) ? expf(logit - m) : 0.f;
    float s = ev;
    #pragma unroll
    for (int off = 16; off; off >>= 1) s += __shfl_xor_sync(FULL, s, off);
    float p = ev / s;
    float biased = (lane < ROUTED) ? (p + ebias[lane]) : -1e30f;

    // top-3 (lowest index wins ties, matching jax.lax.top_k)
    float cur = biased;
    float tv0, tv1, tv2; int ti0, ti1, ti2;
    #pragma unroll
    for (int r = 0; r < 3; r++) {
        float bv = cur; int bi = lane;
        #pragma unroll
        for (int off = 16; off; off >>= 1) {
            float ov = __shfl_down_sync(FULL, bv, off);
            int   oi = __shfl_down_sync(FULL, bi, off);
            if (ov > bv || (ov == bv && oi < bi)) { bv = ov; bi = oi; }
        }
        bv = __shfl_sync(FULL, bv, 0);
        bi = __shfl_sync(FULL, bi, 0);
        if (r == 0) { tv0 = bv; ti0 = bi; }
        else if (r == 1) { tv1 = bv; ti1 = bi; }
        else { tv2 = bv; ti2 = bi; }
        if (lane == bi) cur = -1e30f;
    }

    float inv = 0.75f / (tv0 + tv1 + tv2);

    if (write_rw) {
        float v = 0.f;
        if (lane == 0)        v = 0.25f;
        if (lane == ti0 + 1)  v = tv0 * inv;
        if (lane == ti1 + 1)  v = tv1 * inv;
        if (lane == ti2 + 1)  v = tv2 * inv;
        rw[n * E + lane] = v;
    }

    // append (token, slot, gate) to 4 expert lists (experts distinct per token)
    if (lane < 4) {
        int eidx; float g;
        if (lane == 0)      { eidx = 0;       g = 0.25f; }
        else if (lane == 1) { eidx = ti0 + 1; g = tv0 * inv; }
        else if (lane == 2) { eidx = ti1 + 1; g = tv1 * inv; }
        else                { eidx = ti2 + 1; g = tv2 * inv; }
        int pos = atomicAdd(&g_counts[eidx], 1);
        g_tok[eidx * MAXT + pos] = n | (lane << 16);
        g_gw [eidx * MAXT + pos] = g;
    }
}

// ---------------- Expert compute: block = (expert, 32-token tile) ----------------
__device__ __forceinline__ float gelu_tanh(float v) {
    // jax.nn.gelu approximate=True
    return 0.5f * v * (1.f + tanhf(0.7978845608028654f * (v + 0.044715f * v * v * v)));
}

extern __shared__ float dyn_smem[];

__global__ __launch_bounds__(256, 2)
void expert_kernel(const float* __restrict__ x,
                   const float* __restrict__ W1, const float* __restrict__ b1,
                   const float* __restrict__ W2, const float* __restrict__ b2)
{
    int e    = blockIdx.y;
    int cnt  = g_counts[e];
    int base = blockIdx.x * TT;
    if (base >= cnt) return;
    int nt = min(TT, cnt - base);
    int tid = threadIdx.x;

    float* xsT  = dyn_smem;            // [C][PAD]  x transposed: xsT[k][t]
    float* hidT = dyn_smem + C * PAD;  // [C][PAD]  hidden chunk transposed: hidT[j][t]

    __shared__ int   s_tok[TT];
    __shared__ int   s_slot[TT];
    __shared__ float s_g[TT];

    if (tid < TT) {
        if (tid < nt) {
            int ent = g_tok[e * MAXT + base + tid];
            s_tok[tid]  = ent & 0xFFFF;
            s_slot[tid] = ent >> 16;
            s_g[tid]    = g_gw[e * MAXT + base + tid];
        } else {
            s_tok[tid] = 0; s_slot[tid] = 0; s_g[tid] = 0.f;
        }
    }
    __syncthreads();

    // stage X tile transposed (k-major rows, tokens contiguous)
    #pragma unroll 4
    for (int i = 0; i < TT; i++) {
        float v = (i < nt) ? x[s_tok[i] * C + tid] : 0.f;
        xsT[tid * PAD + i] = v;
    }

    float outv[TT];
    float b2v = b2[e * C + tid];
    #pragma unroll
    for (int t = 0; t < TT; t++) outv[t] = b2v;

    __syncthreads();

    #pragma unroll 1
    for (int chunk = 0; chunk < H / C; chunk++) {
        int h0 = chunk * C;

        // GEMM1: hid[t][h0+tid] = gelu( sum_k xs[t][k] * W1[e][k][h0+tid] + b1 )
        float acc[TT];
        float b1v = b1[e * H + h0 + tid];
        #pragma unroll
        for (int t = 0; t < TT; t++) acc[t] = b1v;

        const float* w1p = W1 + (size_t)e * C * H + h0 + tid;
        #pragma unroll 2
        for (int k = 0; k < C; k++) {
            float w = w1p[(size_t)k * H];
            const float4* xr = (const float4*)(xsT + k * PAD);
            #pragma unroll
            for (int q = 0; q < TT / 4; q++) {
                float4 xv = xr[q];
                acc[4*q+0] = fmaf(xv.x, w, acc[4*q+0]);
                acc[4*q+1] = fmaf(xv.y, w, acc[4*q+1]);
                acc[4*q+2] = fmaf(xv.z, w, acc[4*q+2]);
                acc[4*q+3] = fmaf(xv.w, w, acc[4*q+3]);
            }
        }

        #pragma unroll
        for (int t = 0; t < TT; t++) acc[t] = gelu_tanh(acc[t]);
        #pragma unroll
        for (int q = 0; q < TT / 4; q++) {
            float4 hv = make_float4(acc[4*q+0], acc[4*q+1], acc[4*q+2], acc[4*q+3]);
            *(float4*)(hidT + tid * PAD + 4 * q) = hv;
        }
        __syncthreads();

        // GEMM2: out[t][tid] += sum_j hid[t][j] * W2[e][h0+j][tid]
        const float* w2p = W2 + (size_t)e * H * C + (size_t)h0 * C + tid;
        #pragma unroll 2
        for (int j = 0; j < C; j++) {
            float w = w2p[(size_t)j * C];
            const float4* hr = (const float4*)(hidT + j * PAD);
            #pragma unroll
            for (int q = 0; q < TT / 4; q++) {
                float4 hv = hr[q];
                outv[4*q+0] = fmaf(hv.x, w, outv[4*q+0]);
                outv[4*q+1] = fmaf(hv.y, w, outv[4*q+1]);
                outv[4*q+2] = fmaf(hv.z, w, outv[4*q+2]);
                outv[4*q+3] = fmaf(hv.w, w, outv[4*q+3]);
            }
        }
        __syncthreads();
    }

    // write gate-scaled results into private (slot, token) scratch rows
    for (int t = 0; t < nt; t++) {
        g_scratch[((size_t)s_slot[t] * N_TOK + s_tok[t]) * C + tid] = s_g[t] * outv[t];
    }
}

// ---------------- Final reduce over 4 slots ----------------
__global__ void reduce_kernel(float* __restrict__ out)
{
    const int NC = N_TOK * C;
    int idx = blockIdx.x * blockDim.x + threadIdx.x;
    if (idx < NC) {
        out[idx] = g_scratch[idx] + g_scratch[idx + NC]
                 + g_scratch[idx + 2 * NC] + g_scratch[idx + 3 * NC];
    }
}

extern "C" void kernel_launch(void* const* d_in, const int* in_sizes, int n_in,
                              void* d_out, int out_size)
{
    const float* x   = (const float*)d_in[0];
    const float* gW  = (const float*)d_in[1];
    const float* gb  = (const float*)d_in[2];
    const float* eb  = (const float*)d_in[3];
    const float* W1  = (const float*)d_in[4];
    const float* b1  = (const float*)d_in[5];
    const float* W2  = (const float*)d_in[6];
    const float* b2  = (const float*)d_in[7];
    float* out = (float*)d_out;

    int write_rw = (out_size >= N_TOK * C + N_TOK * E) ? 1 : 0;
    float* rw = out + N_TOK * C;

    const int smem_bytes = 2 * C * PAD * sizeof(float);  // 73728
    cudaFuncSetAttribute(expert_kernel,
                         cudaFuncAttributeMaxDynamicSharedMemorySize, smem_bytes);

    zero_counts_kernel<<<1, 32>>>();
    router_kernel<<<N_TOK, 32>>>(x, gW, gb, eb, rw, write_rw);

    dim3 grid(N_TOK / TT, E);   // 128 tiles x 32 experts; inactive tiles exit early
    expert_kernel<<<grid, 256, smem_bytes>>>(x, W1, b1, W2, b2);

    reduce_kernel<<<(N_TOK * C + 255) / 256, 256>>>(out);
}

// round 2
// speedup vs baseline: 1.0177x; 1.0177x over previous
#include <cuda_runtime.h>
#include <math.h>

#define N_TOK 4096
#define C 256
#define H 1024
#define E 32
#define ROUTED 31
#define TT 32
#define MAXT 4096
#define PAD (TT + 4)   // 36 floats/row -> 144B stride, 16B aligned

// ---- device scratch (no allocation allowed) ----
__device__ int   g_counts[E];
__device__ int   g_tok[E * MAXT];     // token index | (slot << 16)
__device__ float g_gw [E * MAXT];     // gate weight
__device__ float g_scratch[4 * N_TOK * C];   // [slot][n][c], 16MB

__global__ void zero_counts_kernel() {
    if (threadIdx.x < E) g_counts[threadIdx.x] = 0;
}

// ---------------- Router: 1 warp per token ----------------
__global__ void router_kernel(const float* __restrict__ x,
                              const float* __restrict__ gW,
                              const float* __restrict__ gb,
                              const float* __restrict__ ebias,
                              float* __restrict__ rw, int write_rw)
{
    const unsigned FULL = 0xffffffffu;
    int n    = blockIdx.x;
    int lane = threadIdx.x;

    __shared__ float xrow[C];
    for (int i = lane; i < C; i += 32) xrow[i] = x[n * C + i];
    __syncwarp();

    float logit = -1e30f;
    if (lane < ROUTED) {
        float acc = gb[lane];
        #pragma unroll 8
        for (int k = 0; k < C; k++) acc = fmaf(xrow[k], gW[k * ROUTED + lane], acc);
        logit = acc;
    }

    // softmax over 31 routed logits
    float m = logit;
    #pragma unroll
    for (int off = 16; off; off >>= 1) m = fmaxf(m, __shfl_xor_sync(FULL, m, off));
    float ev = (lane < ROUTED) ? expf(logit - m) : 0.f;
    float s = ev;
    #pragma unroll
    for (int off = 16; off; off >>= 1) s += __shfl_xor_sync(FULL, s, off);
    float p = ev / s;
    float biased = (lane < ROUTED) ? (p + ebias[lane]) : -1e30f;

    // top-3 (lowest index wins ties, matching jax.lax.top_k)
    float cur = biased;
    float tv0, tv1, tv2; int ti0, ti1, ti2;
    #pragma unroll
    for (int r = 0; r < 3; r++) {
        float bv = cur; int bi = lane;
        #pragma unroll
        for (int off = 16; off; off >>= 1) {
            float ov = __shfl_down_sync(FULL, bv, off);
            int   oi = __shfl_down_sync(FULL, bi, off);
            if (ov > bv || (ov == bv && oi < bi)) { bv = ov; bi = oi; }
        }
        bv = __shfl_sync(FULL, bv, 0);
        bi = __shfl_sync(FULL, bi, 0);
        if (r == 0) { tv0 = bv; ti0 = bi; }
        else if (r == 1) { tv1 = bv; ti1 = bi; }
        else { tv2 = bv; ti2 = bi; }
        if (lane == bi) cur = -1e30f;
    }

    float inv = 0.75f / (tv0 + tv1 + tv2);

    if (write_rw) {
        float v = 0.f;
        if (lane == 0)        v = 0.25f;
        if (lane == ti0 + 1)  v = tv0 * inv;
        if (lane == ti1 + 1)  v = tv1 * inv;
        if (lane == ti2 + 1)  v = tv2 * inv;
        rw[n * E + lane] = v;
    }

    if (lane < 4) {
        int eidx; float g;
        if (lane == 0)      { eidx = 0;       g = 0.25f; }
        else if (lane == 1) { eidx = ti0 + 1; g = tv0 * inv; }
        else if (lane == 2) { eidx = ti1 + 1; g = tv1 * inv; }
        else                { eidx = ti2 + 1; g = tv2 * inv; }
        int pos = atomicAdd(&g_counts[eidx], 1);
        g_tok[eidx * MAXT + pos] = n | (lane << 16);
        g_gw [eidx * MAXT + pos] = g;
    }
}

// ---------------- Expert compute ----------------
__device__ __forceinline__ float gelu_tanh(float v) {
    float t = 0.7978845608028654f * (v + 0.044715f * v * v * v);
    float th;
    asm("tanh.approx.f32 %0, %1;" : "=f"(th) : "f"(t));
    return 0.5f * v * (1.f + th);
}

__device__ __forceinline__ unsigned long long pack2(float lo, float hi) {
    unsigned long long r;
    asm("mov.b64 %0, {%1, %2};" : "=l"(r) : "f"(lo), "f"(hi));
    return r;
}
__device__ __forceinline__ void unpack2(unsigned long long v, float& lo, float& hi) {
    asm("mov.b64 {%0, %1}, %2;" : "=f"(lo), "=f"(hi) : "l"(v));
}

extern __shared__ float dyn_smem[];

__global__ __launch_bounds__(256, 2)
void expert_kernel(const float* __restrict__ x,
                   const float* __restrict__ W1, const float* __restrict__ b1,
                   const float* __restrict__ W2, const float* __restrict__ b2)
{
    int e    = blockIdx.y;
    int cnt  = g_counts[e];
    int base = blockIdx.x * TT;
    if (base >= cnt) return;
    int nt = min(TT, cnt - base);
    int tid = threadIdx.x;

    float* xsT  = dyn_smem;            // [C][PAD]  xsT[k][t]
    float* hidT = dyn_smem + C * PAD;  // [C][PAD]  hidT[j][t]
    unsigned xbase = (unsigned)__cvta_generic_to_shared(xsT);
    unsigned hbase = (unsigned)__cvta_generic_to_shared(hidT);

    __shared__ int   s_tok[TT];
    __shared__ int   s_slot[TT];
    __shared__ float s_g[TT];

    if (tid < TT) {
        if (tid < nt) {
            int ent = g_tok[e * MAXT + base + tid];
            s_tok[tid]  = ent & 0xFFFF;
            s_slot[tid] = ent >> 16;
            s_g[tid]    = g_gw[e * MAXT + base + tid];
        } else {
            s_tok[tid] = 0; s_slot[tid] = 0; s_g[tid] = 0.f;
        }
    }
    __syncthreads();

    // stage X tile transposed
    #pragma unroll 4
    for (int i = 0; i < TT; i++) {
        float v = (i < nt) ? x[s_tok[i] * C + tid] : 0.f;
        xsT[tid * PAD + i] = v;
    }

    unsigned long long outp[TT / 2];
    {
        float b2v = b2[e * C + tid];
        unsigned long long b2p = pack2(b2v, b2v);
        #pragma unroll
        for (int q = 0; q < TT / 2; q++) outp[q] = b2p;
    }

    __syncthreads();

    #pragma unroll 1
    for (int chunk = 0; chunk < H / C; chunk++) {
        int h0 = chunk * C;

        // GEMM1: hid[t][h0+tid] = gelu( sum_k xsT[k][t] * W1[e][k][h0+tid] + b1 )
        unsigned long long acc[TT / 2];
        {
            float b1v = b1[e * H + h0 + tid];
            unsigned long long b1p = pack2(b1v, b1v);
            #pragma unroll
            for (int q = 0; q < TT / 2; q++) acc[q] = b1p;
        }

        const float* w1p = W1 + (size_t)e * C * H + h0 + tid;
        #pragma unroll 2
        for (int k = 0; k < C; k++) {
            float w = w1p[(size_t)k * H];
            unsigned long long wp;
            asm("mov.b64 %0, {%1, %1};" : "=l"(wp) : "f"(w));
            unsigned row = xbase + k * (PAD * 4);
            #pragma unroll
            for (int q = 0; q < 8; q++) {
                unsigned long long a0, a1;
                asm("ld.shared.v2.b64 {%0, %1}, [%2];"
                    : "=l"(a0), "=l"(a1) : "r"(row + q * 16));
                asm("fma.rn.f32x2 %0, %1, %2, %0;" : "+l"(acc[2*q])   : "l"(a0), "l"(wp));
                asm("fma.rn.f32x2 %0, %1, %2, %0;" : "+l"(acc[2*q+1]) : "l"(a1), "l"(wp));
            }
        }

        // gelu + store hidden transposed
        #pragma unroll
        for (int q = 0; q < TT / 2; q++) {
            float lo, hi;
            unpack2(acc[q], lo, hi);
            lo = gelu_tanh(lo);
            hi = gelu_tanh(hi);
            unsigned long long g = pack2(lo, hi);
            asm volatile("st.shared.b64 [%0], %1;"
                         :: "r"(hbase + (tid * PAD + 2 * q) * 4), "l"(g) : "memory");
        }
        __syncthreads();

        // GEMM2: out[t][tid] += sum_j hidT[j][t] * W2[e][h0+j][tid]
        const float* w2p = W2 + (size_t)e * H * C + (size_t)h0 * C + tid;
        #pragma unroll 2
        for (int j = 0; j < C; j++) {
            float w = w2p[(size_t)j * C];
            unsigned long long wp;
            asm("mov.b64 %0, {%1, %1};" : "=l"(wp) : "f"(w));
            unsigned row = hbase + j * (PAD * 4);
            #pragma unroll
            for (int q = 0; q < 8; q++) {
                unsigned long long a0, a1;
                asm("ld.shared.v2.b64 {%0, %1}, [%2];"
                    : "=l"(a0), "=l"(a1) : "r"(row + q * 16));
                asm("fma.rn.f32x2 %0, %1, %2, %0;" : "+l"(outp[2*q])   : "l"(a0), "l"(wp));
                asm("fma.rn.f32x2 %0, %1, %2, %0;" : "+l"(outp[2*q+1]) : "l"(a1), "l"(wp));
            }
        }
        __syncthreads();
    }

    // write gate-scaled results into private (slot, token) scratch rows
    #pragma unroll
    for (int q = 0; q < TT / 2; q++) {
        float lo, hi;
        unpack2(outp[q], lo, hi);
        int t0 = 2 * q, t1 = 2 * q + 1;
        if (t0 < nt)
            g_scratch[((size_t)s_slot[t0] * N_TOK + s_tok[t0]) * C + tid] = s_g[t0] * lo;
        if (t1 < nt)
            g_scratch[((size_t)s_slot[t1] * N_TOK + s_tok[t1]) * C + tid] = s_g[t1] * hi;
    }
}

// ---------------- Final reduce over 4 slots ----------------
__global__ void reduce_kernel(float* __restrict__ out)
{
    const int NC = N_TOK * C;
    int idx = blockIdx.x * blockDim.x + threadIdx.x;
    if (idx < NC) {
        out[idx] = g_scratch[idx] + g_scratch[idx + NC]
                 + g_scratch[idx + 2 * NC] + g_scratch[idx + 3 * NC];
    }
}

extern "C" void kernel_launch(void* const* d_in, const int* in_sizes, int n_in,
                              void* d_out, int out_size)
{
    const float* x   = (const float*)d_in[0];
    const float* gW  = (const float*)d_in[1];
    const float* gb  = (const float*)d_in[2];
    const float* eb  = (const float*)d_in[3];
    const float* W1  = (const float*)d_in[4];
    const float* b1  = (const float*)d_in[5];
    const float* W2  = (const float*)d_in[6];
    const float* b2  = (const float*)d_in[7];
    float* out = (float*)d_out;

    int write_rw = (out_size >= N_TOK * C + N_TOK * E) ? 1 : 0;
    float* rw = out + N_TOK * C;

    const int smem_bytes = 2 * C * PAD * sizeof(float);  // 73728
    cudaFuncSetAttribute(expert_kernel,
                         cudaFuncAttributeMaxDynamicSharedMemorySize, smem_bytes);

    zero_counts_kernel<<<1, 32>>>();
    router_kernel<<<N_TOK, 32>>>(x, gW, gb, eb, rw, write_rw);

    dim3 grid(N_TOK / TT, E);
    expert_kernel<<<grid, 256, smem_bytes>>>(x, W1, b1, W2, b2);

    reduce_kernel<<<(N_TOK * C + 255) / 256, 256>>>(out);
}

// round 3
// speedup vs baseline: 1.6938x; 1.6644x over previous
#include <cuda_runtime.h>
#include <math.h>

#define N_TOK 4096
#define C 256
#define H 1024
#define E 32
#define ROUTED 31
#define TT 32
#define MAXT 4096
#define PAD (TT + 4)   // 36 floats/row -> 144B stride, 16B aligned
#define KU 8           // k-group / prefetch depth

// ---- device scratch (no allocation allowed) ----
__device__ int   g_counts[E];
__device__ int   g_tok[E * MAXT];     // token index | (slot << 16)
__device__ float g_gw [E * MAXT];     // gate weight
__device__ float g_scratch[4 * N_TOK * C];   // [slot][n][c], 16MB

__global__ void zero_counts_kernel() {
    if (threadIdx.x < E) g_counts[threadIdx.x] = 0;
}

// ---------------- Router: 1 warp per token ----------------
__global__ void router_kernel(const float* __restrict__ x,
                              const float* __restrict__ gW,
                              const float* __restrict__ gb,
                              const float* __restrict__ ebias,
                              float* __restrict__ rw, int write_rw)
{
    const unsigned FULL = 0xffffffffu;
    int n    = blockIdx.x;
    int lane = threadIdx.x;

    __shared__ float xrow[C];
    for (int i = lane; i < C; i += 32) xrow[i] = x[n * C + i];
    __syncwarp();

    float logit = -1e30f;
    if (lane < ROUTED) {
        float acc = gb[lane];
        #pragma unroll 8
        for (int k = 0; k < C; k++) acc = fmaf(xrow[k], gW[k * ROUTED + lane], acc);
        logit = acc;
    }

    float m = logit;
    #pragma unroll
    for (int off = 16; off; off >>= 1) m = fmaxf(m, __shfl_xor_sync(FULL, m, off));
    float ev = (lane < ROUTED) ? expf(logit - m) : 0.f;
    float s = ev;
    #pragma unroll
    for (int off = 16; off; off >>= 1) s += __shfl_xor_sync(FULL, s, off);
    float p = ev / s;
    float biased = (lane < ROUTED) ? (p + ebias[lane]) : -1e30f;

    float cur = biased;
    float tv0, tv1, tv2; int ti0, ti1, ti2;
    #pragma unroll
    for (int r = 0; r < 3; r++) {
        float bv = cur; int bi = lane;
        #pragma unroll
        for (int off = 16; off; off >>= 1) {
            float ov = __shfl_down_sync(FULL, bv, off);
            int   oi = __shfl_down_sync(FULL, bi, off);
            if (ov > bv || (ov == bv && oi < bi)) { bv = ov; bi = oi; }
        }
        bv = __shfl_sync(FULL, bv, 0);
        bi = __shfl_sync(FULL, bi, 0);
        if (r == 0) { tv0 = bv; ti0 = bi; }
        else if (r == 1) { tv1 = bv; ti1 = bi; }
        else { tv2 = bv; ti2 = bi; }
        if (lane == bi) cur = -1e30f;
    }

    float inv = 0.75f / (tv0 + tv1 + tv2);

    if (write_rw) {
        float v = 0.f;
        if (lane == 0)        v = 0.25f;
        if (lane == ti0 + 1)  v = tv0 * inv;
        if (lane == ti1 + 1)  v = tv1 * inv;
        if (lane == ti2 + 1)  v = tv2 * inv;
        rw[n * E + lane] = v;
    }

    if (lane < 4) {
        int eidx; float g;
        if (lane == 0)      { eidx = 0;       g = 0.25f; }
        else if (lane == 1) { eidx = ti0 + 1; g = tv0 * inv; }
        else if (lane == 2) { eidx = ti1 + 1; g = tv1 * inv; }
        else                { eidx = ti2 + 1; g = tv2 * inv; }
        int pos = atomicAdd(&g_counts[eidx], 1);
        g_tok[eidx * MAXT + pos] = n | (lane << 16);
        g_gw [eidx * MAXT + pos] = g;
    }
}

// ---------------- Expert compute ----------------
__device__ __forceinline__ float gelu_tanh(float v) {
    float t = 0.7978845608028654f * (v + 0.044715f * v * v * v);
    float th;
    asm("tanh.approx.f32 %0, %1;" : "=f"(th) : "f"(t));
    return 0.5f * v * (1.f + th);
}

__device__ __forceinline__ unsigned long long pack2(float lo, float hi) {
    unsigned long long r;
    asm("mov.b64 %0, {%1, %2};" : "=l"(r) : "f"(lo), "f"(hi));
    return r;
}
__device__ __forceinline__ void unpack2(unsigned long long v, float& lo, float& hi) {
    asm("mov.b64 {%0, %1}, %2;" : "=f"(lo), "=f"(hi) : "l"(v));
}

// one k-step: 8x ld.shared.v2.b64 + 16x fma.rn.f32x2 against packed weight wp
__device__ __forceinline__ void fma_row(unsigned long long* acc, unsigned row, float w) {
    unsigned long long wp;
    asm("mov.b64 %0, {%1, %1};" : "=l"(wp) : "f"(w));
    #pragma unroll
    for (int q = 0; q < 8; q++) {
        unsigned long long a0, a1;
        asm("ld.shared.v2.b64 {%0, %1}, [%2];"
            : "=l"(a0), "=l"(a1) : "r"(row + q * 16));
        asm("fma.rn.f32x2 %0, %1, %2, %0;" : "+l"(acc[2*q])   : "l"(a0), "l"(wp));
        asm("fma.rn.f32x2 %0, %1, %2, %0;" : "+l"(acc[2*q+1]) : "l"(a1), "l"(wp));
    }
}

extern __shared__ float dyn_smem[];

__global__ __launch_bounds__(256, 2)
void expert_kernel(const float* __restrict__ x,
                   const float* __restrict__ W1, const float* __restrict__ b1,
                   const float* __restrict__ W2, const float* __restrict__ b2)
{
    int e    = blockIdx.y;
    int cnt  = g_counts[e];
    int base = blockIdx.x * TT;
    if (base >= cnt) return;
    int nt = min(TT, cnt - base);
    int tid = threadIdx.x;

    float* xsT  = dyn_smem;            // [C][PAD]  xsT[k][t]
    float* hidT = dyn_smem + C * PAD;  // [C][PAD]  hidT[j][t]
    unsigned xbase = (unsigned)__cvta_generic_to_shared(xsT);
    unsigned hbase = (unsigned)__cvta_generic_to_shared(hidT);

    __shared__ int   s_tok[TT];
    __shared__ int   s_slot[TT];
    __shared__ float s_g[TT];

    if (tid < TT) {
        if (tid < nt) {
            int ent = g_tok[e * MAXT + base + tid];
            s_tok[tid]  = ent & 0xFFFF;
            s_slot[tid] = ent >> 16;
            s_g[tid]    = g_gw[e * MAXT + base + tid];
        } else {
            s_tok[tid] = 0; s_slot[tid] = 0; s_g[tid] = 0.f;
        }
    }
    __syncthreads();

    #pragma unroll 4
    for (int i = 0; i < TT; i++) {
        float v = (i < nt) ? x[s_tok[i] * C + tid] : 0.f;
        xsT[tid * PAD + i] = v;
    }

    unsigned long long outp[TT / 2];
    {
        float b2v = b2[e * C + tid];
        unsigned long long b2p = pack2(b2v, b2v);
        #pragma unroll
        for (int q = 0; q < TT / 2; q++) outp[q] = b2p;
    }

    __syncthreads();

    #pragma unroll 1
    for (int chunk = 0; chunk < H / C; chunk++) {
        int h0 = chunk * C;

        // ---- GEMM1: hid = gelu(X * W1 + b1), software-pipelined weight loads ----
        unsigned long long acc[TT / 2];
        {
            float b1v = b1[e * H + h0 + tid];
            unsigned long long b1p = pack2(b1v, b1v);
            #pragma unroll
            for (int q = 0; q < TT / 2; q++) acc[q] = b1p;
        }

        const float* w1p = W1 + (size_t)e * C * H + h0 + tid;
        float wbuf[KU];
        #pragma unroll
        for (int u = 0; u < KU; u++) wbuf[u] = __ldg(w1p + (size_t)u * H);

        #pragma unroll 1
        for (int kk = 0; kk < C; kk += KU) {
            float wn[KU];
            int kn = (kk + KU < C) ? (kk + KU) : 0;   // last group prefetches row 0 (discarded)
            #pragma unroll
            for (int u = 0; u < KU; u++) wn[u] = __ldg(w1p + (size_t)(kn + u) * H);
            #pragma unroll
            for (int u = 0; u < KU; u++)
                fma_row(acc, xbase + (kk + u) * (PAD * 4), wbuf[u]);
            #pragma unroll
            for (int u = 0; u < KU; u++) wbuf[u] = wn[u];
        }

        #pragma unroll
        for (int q = 0; q < TT / 2; q++) {
            float lo, hi;
            unpack2(acc[q], lo, hi);
            lo = gelu_tanh(lo);
            hi = gelu_tanh(hi);
            unsigned long long g = pack2(lo, hi);
            asm volatile("st.shared.b64 [%0], %1;"
                         :: "r"(hbase + (tid * PAD + 2 * q) * 4), "l"(g) : "memory");
        }
        __syncthreads();

        // ---- GEMM2: out += hid * W2, software-pipelined weight loads ----
        const float* w2p = W2 + (size_t)e * H * C + (size_t)h0 * C + tid;
        #pragma unroll
        for (int u = 0; u < KU; u++) wbuf[u] = __ldg(w2p + (size_t)u * C);

        #pragma unroll 1
        for (int jj = 0; jj < C; jj += KU) {
            float wn[KU];
            int jn = (jj + KU < C) ? (jj + KU) : 0;
            #pragma unroll
            for (int u = 0; u < KU; u++) wn[u] = __ldg(w2p + (size_t)(jn + u) * C);
            #pragma unroll
            for (int u = 0; u < KU; u++)
                fma_row(outp, hbase + (jj + u) * (PAD * 4), wbuf[u]);
            #pragma unroll
            for (int u = 0; u < KU; u++) wbuf[u] = wn[u];
        }
        __syncthreads();
    }

    #pragma unroll
    for (int q = 0; q < TT / 2; q++) {
        float lo, hi;
        unpack2(outp[q], lo, hi);
        int t0 = 2 * q, t1 = 2 * q + 1;
        if (t0 < nt)
            g_scratch[((size_t)s_slot[t0] * N_TOK + s_tok[t0]) * C + tid] = s_g[t0] * lo;
        if (t1 < nt)
            g_scratch[((size_t)s_slot[t1] * N_TOK + s_tok[t1]) * C + tid] = s_g[t1] * hi;
    }
}

// ---------------- Final reduce over 4 slots ----------------
__global__ void reduce_kernel(float* __restrict__ out)
{
    const int NC = N_TOK * C;
    int idx = blockIdx.x * blockDim.x + threadIdx.x;
    if (idx < NC) {
        out[idx] = g_scratch[idx] + g_scratch[idx + NC]
                 + g_scratch[idx + 2 * NC] + g_scratch[idx + 3 * NC];
    }
}

extern "C" void kernel_launch(void* const* d_in, const int* in_sizes, int n_in,
                              void* d_out, int out_size)
{
    const float* x   = (const float*)d_in[0];
    const float* gW  = (const float*)d_in[1];
    const float* gb  = (const float*)d_in[2];
    const float* eb  = (const float*)d_in[3];
    const float* W1  = (const float*)d_in[4];
    const float* b1  = (const float*)d_in[5];
    const float* W2  = (const float*)d_in[6];
    const float* b2  = (const float*)d_in[7];
    float* out = (float*)d_out;

    int write_rw = (out_size >= N_TOK * C + N_TOK * E) ? 1 : 0;
    float* rw = out + N_TOK * C;

    const int smem_bytes = 2 * C * PAD * sizeof(float);  // 73728
    cudaFuncSetAttribute(expert_kernel,
                         cudaFuncAttributeMaxDynamicSharedMemorySize, smem_bytes);

    zero_counts_kernel<<<1, 32>>>();
    router_kernel<<<N_TOK, 32>>>(x, gW, gb, eb, rw, write_rw);

    dim3 grid(N_TOK / TT, E);
    expert_kernel<<<grid, 256, smem_bytes>>>(x, W1, b1, W2, b2);

    reduce_kernel<<<(N_TOK * C + 255) / 256, 256>>>(out);
}